// round 13
// baseline (speedup 1.0000x reference)
#include <cuda_runtime.h>
#include <cuda_fp16.h>
#include <math.h>
#include <stdint.h>

// Problem constants
#define BATCH 16
#define TT    4096
#define INF   256
#define OUTF  256
#define HF    512
#define MTOT  (BATCH * TT)              // 65536
#define K2    1280                      // GEMM2 K = 1024 interleaved ys + 256 X
#define Y_ELEMS ((long long)MTOT * OUTF)
#define NQ    4                         // pipeline quarters
#define MQ    (MTOT / NQ)               // 16384 rows per quarter
#define BQ    (BATCH / NQ)              // 4 batches per quarter

// ---------------------------------------------------------------------------
// Scratch (__device__ globals; no allocation APIs)
// ---------------------------------------------------------------------------
__device__ __align__(16) __half2 g_U2[(size_t)MTOT * HF];     // interleaved (re,im) u
__device__ __align__(16) __half  g_A2[(size_t)MTOT * K2];     // fp16 activations
__device__ __align__(16) __half  g_B[1024 * 256];             // interleaved Bcat rows
__device__ __align__(16) __half  g_W[256 * K2];               // interleaved W cols
__device__ float2 g_lam[HF];
__device__ float2 g_cvec[HF];
__device__ float  g_gamma[HF];

// ---------------------------------------------------------------------------
// Streams / events for fork-join overlap (created at load time, before the
// harness's memory checkpoints; streams/events are not device-mem allocs).
// ---------------------------------------------------------------------------
struct AsyncRes {
    cudaStream_t s1;
    cudaEvent_t evFork;
    cudaEvent_t evC[NQ];    // convx quarter done (s1)
    cudaEvent_t evG1[NQ];   // gemm1 quarter done (s0)
    cudaEvent_t evS[NQ];    // scan quarter done (s1)
    AsyncRes() {
        cudaStreamCreateWithFlags(&s1, cudaStreamNonBlocking);
        cudaEventCreateWithFlags(&evFork, cudaEventDisableTiming);
        for (int i = 0; i < NQ; i++) {
            cudaEventCreateWithFlags(&evC[i], cudaEventDisableTiming);
            cudaEventCreateWithFlags(&evG1[i], cudaEventDisableTiming);
            cudaEventCreateWithFlags(&evS[i], cudaEventDisableTiming);
        }
    }
};
static AsyncRes g_ar;

// ---------------------------------------------------------------------------
// PTX helpers (generic PTX only; no sm_103a-only features)
// ---------------------------------------------------------------------------
__device__ __forceinline__ uint32_t smem_u32(const void* p) {
    uint32_t a;
    asm("{ .reg .u64 t; cvta.to.shared.u64 t, %1; cvt.u32.u64 %0, t; }" : "=r"(a) : "l"(p));
    return a;
}
__device__ __forceinline__ void ldsm_x4(uint32_t* r, uint32_t addr) {
    asm volatile("ldmatrix.sync.aligned.m8n8.x4.shared.b16 {%0,%1,%2,%3}, [%4];"
                 : "=r"(r[0]), "=r"(r[1]), "=r"(r[2]), "=r"(r[3]) : "r"(addr));
}
__device__ __forceinline__ void mma16816(float* c, const uint32_t* a, uint32_t b0, uint32_t b1) {
    asm volatile(
        "mma.sync.aligned.m16n8k16.row.col.f32.f16.f16.f32 "
        "{%0,%1,%2,%3}, {%4,%5,%6,%7}, {%8,%9}, {%0,%1,%2,%3};"
        : "+f"(c[0]), "+f"(c[1]), "+f"(c[2]), "+f"(c[3])
        : "r"(a[0]), "r"(a[1]), "r"(a[2]), "r"(a[3]), "r"(b0), "r"(b1));
}
__device__ __forceinline__ void cp_async16(uint32_t sdst, const void* gsrc) {
    asm volatile("cp.async.cg.shared.global [%0], [%1], 16;"
                 :: "r"(sdst), "l"(__cvta_generic_to_global(gsrc)) : "memory");
}
#define CP_COMMIT()  asm volatile("cp.async.commit_group;" ::: "memory")
#define CP_WAIT(n)   asm volatile("cp.async.wait_group %0;" :: "n"(n) : "memory")

// ---------------------------------------------------------------------------
// SMEM: 2 stages x 2 tiles of 128 rows x 32 fp16, row stride 80 B
// ---------------------------------------------------------------------------
#define TSTR   80
#define TILE_B (128 * TSTR)             // 10240
#define S_A    0
#define S_B    (TILE_B)
#define STAGE_B (2 * TILE_B)            // 20480
#define SMEM_BYTES (2 * STAGE_B)        // 40960

// 128 threads: 512 16B units, 4 iters.
__device__ __forceinline__ void ld_tile_async(uint32_t sbase, const __half* __restrict__ g,
                                              int ld, int tid) {
#pragma unroll
    for (int it = 0; it < 4; it++) {
        int u = tid + it * 128;
        int r = u >> 2, j = u & 3;
        cp_async16(sbase + r * TSTR + j * 16, g + (size_t)r * ld + j * 8);
    }
}

__device__ __forceinline__ void ld_stage(uint32_t sb,
                                         const __half* A, int lda,
                                         const __half* B, int ldb,
                                         int kc, int tid) {
    ld_tile_async(sb + S_A, A + kc * 32, lda, tid);
    ld_tile_async(sb + S_B, B + kc * 32, ldb, tid);
}

// Compute one BK=32 chunk with 64x64 warp tiles (4 warps, 2m x 2n grid).
__device__ __forceinline__ void compute_chunk(float acc[4][8][4], uint32_t sb,
                                              int lane, int wm, int wn) {
    const uint32_t a_coff = (uint32_t)((lane >> 4) << 4);
    const int a_rl = lane & 15;
    const int b_rowl = (lane & 7) + ((lane >> 4) << 3);
    const uint32_t b_coff = (uint32_t)(((lane >> 3) & 1) << 4);

#pragma unroll
    for (int k16 = 0; k16 < 2; k16++) {
        const uint32_t koff = (uint32_t)(k16 * 32);
        uint32_t ah[4][4], bx[4][4];

#pragma unroll
        for (int mf = 0; mf < 4; mf++)
            ldsm_x4(ah[mf], sb + S_A + (uint32_t)(wm * 64 + mf * 16 + a_rl) * TSTR + koff + a_coff);
#pragma unroll
        for (int ng = 0; ng < 4; ng++)
            ldsm_x4(bx[ng], sb + S_B + (uint32_t)(wn * 64 + ng * 16 + b_rowl) * TSTR + koff + b_coff);

#pragma unroll
        for (int mf = 0; mf < 4; mf++)
#pragma unroll
            for (int ng = 0; ng < 4; ng++) {
                mma16816(acc[mf][2 * ng],     ah[mf], bx[ng][0], bx[ng][1]);
                mma16816(acc[mf][2 * ng + 1], ah[mf], bx[ng][2], bx[ng][3]);
            }
    }
}

// Double-buffered GEMM core (128 threads).
__device__ __forceinline__ void gemm_core(
    float acc[4][8][4],
    const __half* __restrict__ A, int lda,
    const __half* __restrict__ B, int ldb,
    int kChunks, uint32_t sb, int tid) {

    const int lane = tid & 31;
    const int warp = tid >> 5;
    const int wm = warp & 1, wn = warp >> 1;

    ld_stage(sb, A, lda, B, ldb, 0, tid);
    CP_COMMIT();

    for (int kc = 0; kc < kChunks; kc++) {
        if (kc + 1 < kChunks) {
            ld_stage(sb + ((kc + 1) & 1) * STAGE_B, A, lda, B, ldb, kc + 1, tid);
            CP_COMMIT();
            CP_WAIT(1);
        } else {
            CP_WAIT(0);
        }
        __syncthreads();
        compute_chunk(acc, sb + (kc & 1) * STAGE_B, lane, wm, wn);
        __syncthreads();
    }
}

// ---------------------------------------------------------------------------
// Prep kernels
// ---------------------------------------------------------------------------
__global__ void prep_kernel(const float* __restrict__ nu_log,
                            const float* __restrict__ theta_log,
                            const float* __restrict__ bh_re,
                            const float* __restrict__ bh_im) {
    int h = threadIdx.x;
    if (h >= HF) return;
    float en = expf(nu_log[h]);
    float et = expf(theta_log[h]);
    float mag = expf(-en);
    float s, c;
    sincosf(et, &s, &c);
    g_lam[h] = make_float2(mag * c, mag * s);
    float gam = sqrtf(fmaxf(0.0f, 1.0f - mag * mag));
    g_gamma[h] = gam;
    g_cvec[h] = make_float2((gam + 1.0f) * bh_re[h], (gam + 1.0f) * bh_im[h]);
}

// Weights. B rows interleaved: row 2h = Bre[h], row 2h+1 = Bim[h] (1024x256).
// W cols interleaved: col 2h = Cre[o][h], col 2h+1 = -Cim[o][h], cols 1024+ = D.
__global__ void wprep_kernel(const float* __restrict__ Bre, const float* __restrict__ Bim,
                             const float* __restrict__ Cre, const float* __restrict__ Cim,
                             const float* __restrict__ D) {
    int n = blockIdx.x * blockDim.x + threadIdx.x;
    if (n < 1024 * 256) {
        int r = n >> 8, i = n & 255;
        int h = r >> 1;
        float v = (r & 1) ? Bim[h * 256 + i] : Bre[h * 256 + i];
        g_B[n] = __float2half(v);
    } else {
        int n2 = n - 1024 * 256;
        if (n2 < 256 * K2) {
            int o = n2 / K2, k = n2 % K2;
            float v;
            if (k < 1024) {
                int h = k >> 1;
                v = (k & 1) ? -Cim[o * 512 + h] : Cre[o * 512 + h];
            } else {
                v = D[o * 256 + (k - 1024)];
            }
            g_W[n2] = __float2half(v);
        }
    }
}

// X -> fp16 into A2 cols [1024..1279]. One quarter per launch (g4Off).
__global__ void convx_kernel(const float* __restrict__ X, long long g4Off) {
    long long g4 = (long long)blockIdx.x * blockDim.x + threadIdx.x + g4Off;
    int m = (int)(g4 >> 6), i = (int)(g4 & 63) * 4;
    float4 v = *reinterpret_cast<const float4*>(X + (size_t)m * INF + i);
    size_t idx = (size_t)m * K2 + 1024 + i;
    *reinterpret_cast<__half2*>(g_A2 + idx)     = __floats2half2_rn(v.x, v.y);
    *reinterpret_cast<__half2*>(g_A2 + idx + 2) = __floats2half2_rn(v.z, v.w);
}

// ---------------------------------------------------------------------------
// GEMM1: u(re,im) interleaved = gamma * (X_f16 . BcatT). Output: g_U2.
// One quarter: grid (8, 128), mYOff in 128-row blocks.
// ---------------------------------------------------------------------------
__global__ __launch_bounds__(128, 2) void gemm1_kernel(int mYOff) {
    extern __shared__ char smem[];
    uint32_t sb = smem_u32(smem);
    const int tid = threadIdx.x;
    const int lane = tid & 31;
    const int warp = tid >> 5;
    const int wm = warp & 1, wn = warp >> 1;
    const int mBase = (blockIdx.y + mYOff) * 128;
    const int colBase = blockIdx.x * 128;

    float acc[4][8][4];
#pragma unroll
    for (int a = 0; a < 4; a++)
#pragma unroll
        for (int b = 0; b < 8; b++)
#pragma unroll
            for (int c = 0; c < 4; c++) acc[a][b][c] = 0.f;

    gemm_core(acc,
              g_A2 + (size_t)mBase * K2 + 1024, K2,
              g_B + (size_t)colBase * 256, 256,
              8, sb, tid);

#pragma unroll
    for (int mf = 0; mf < 4; mf++) {
        int m0 = mBase + wm * 64 + mf * 16 + (lane >> 2);
#pragma unroll
        for (int nf = 0; nf < 8; nf++) {
            int col = colBase + wn * 64 + nf * 8 + (lane & 3) * 2;   // even
            int h = col >> 1;
            float g = g_gamma[h];
            float* c = acc[mf][nf];
            g_U2[(size_t)m0 * HF + h]       = __floats2half2_rn(c[0] * g, c[1] * g);
            g_U2[(size_t)(m0 + 8) * HF + h] = __floats2half2_rn(c[2] * g, c[3] * g);
        }
    }
}

// ---------------------------------------------------------------------------
// Scan: chunked-parallel, 16 chunks of 256 (+32 warmup; lambda^32 ~ 1e-14).
// One quarter (4 batches) per launch via bOff.
// ---------------------------------------------------------------------------
#define SCH   256
#define SWARM 32
__global__ __launch_bounds__(256) void scan_kernel(float* __restrict__ out_hN, int bOff) {
    int g = blockIdx.x * blockDim.x + threadIdx.x;
    int h = g & 511;
    int ch = (g >> 9) & 15;
    int b = (g >> 13) + bOff;
    const float2 lam = g_lam[h];
    const float2 cv = g_cvec[h];
    float hr = 0.f, hi = 0.f;
    const int t0 = ch * SCH;
    const int tw = (ch == 0) ? 0 : t0 - SWARM;
    size_t ub = ((size_t)b * TT + tw) * HF + h;
    for (int t = tw; t < t0; t++) {
        float2 v = __half22float2(g_U2[ub]);
        float vr = v.x + cv.x;
        float vi = v.y + cv.y;
        float nr = fmaf(lam.x, hr, fmaf(-lam.y, hi, vr));
        float ni = fmaf(lam.x, hi, fmaf(lam.y, hr, vi));
        hr = nr; hi = ni; ub += HF;
    }
    size_t arow = ((size_t)b * TT + t0) * K2 + 2 * h;
    for (int t = 0; t < SCH; t++) {
        float2 v = __half22float2(g_U2[ub]);
        float vr = v.x + cv.x;
        float vi = v.y + cv.y;
        float nr = fmaf(lam.x, hr, fmaf(-lam.y, hi, vr));
        float ni = fmaf(lam.x, hi, fmaf(lam.y, hr, vi));
        hr = nr; hi = ni; ub += HF;
        *reinterpret_cast<__half2*>(g_A2 + arow) = __floats2half2_rn(hr, hi);
        arow += K2;
    }
    if (ch == 15) {
        int g2 = b * 512 + h;
        out_hN[g2] = hr;
        out_hN[BATCH * HF + g2] = hi;
    }
}

// ---------------------------------------------------------------------------
// GEMM2: Y[m, 256] = A2 . WcatT + bias (K = 1280). One quarter: grid (2, 128).
// ---------------------------------------------------------------------------
__global__ __launch_bounds__(128, 2) void gemm2_kernel(const float* __restrict__ bias,
                                                       float* __restrict__ Y, int mYOff) {
    extern __shared__ char smem[];
    uint32_t sb = smem_u32(smem);
    const int tid = threadIdx.x;
    const int lane = tid & 31;
    const int warp = tid >> 5;
    const int wm = warp & 1, wn = warp >> 1;
    const int mBase = (blockIdx.y + mYOff) * 128;
    const int colBase = blockIdx.x * 128;

    float acc[4][8][4];
#pragma unroll
    for (int a = 0; a < 4; a++)
#pragma unroll
        for (int b = 0; b < 8; b++)
#pragma unroll
            for (int c = 0; c < 4; c++) acc[a][b][c] = 0.f;

    gemm_core(acc,
              g_A2 + (size_t)mBase * K2, K2,
              g_W + (size_t)colBase * K2, K2,
              40, sb, tid);

#pragma unroll
    for (int mf = 0; mf < 4; mf++) {
        int m0 = mBase + wm * 64 + mf * 16 + (lane >> 2);
#pragma unroll
        for (int nf = 0; nf < 8; nf++) {
            int col = colBase + wn * 64 + nf * 8 + (lane & 3) * 2;
            float b0 = bias[col], b1 = bias[col + 1];
            float* c = acc[mf][nf];
            *reinterpret_cast<float2*>(&Y[(size_t)m0 * OUTF + col]) =
                make_float2(c[0] + b0, c[1] + b1);
            *reinterpret_cast<float2*>(&Y[(size_t)(m0 + 8) * OUTF + col]) =
                make_float2(c[2] + b0, c[3] + b1);
        }
    }
}

// ---------------------------------------------------------------------------
// Launch: 4-quarter software pipeline across 2 streams.
//   s0 (capture stream): prep, wprep, convx_q0, all GEMMs (tensor-pipe bound)
//   s1: convx_q1..q3, scans (memory bound) — overlap with GEMMs
// ---------------------------------------------------------------------------
extern "C" void kernel_launch(void* const* d_in, const int* in_sizes, int n_in,
                              void* d_out, int out_size) {
    const float* X      = (const float*)d_in[0];
    const float* nu_log = (const float*)d_in[1];
    const float* th_log = (const float*)d_in[2];
    const float* Bre    = (const float*)d_in[3];
    const float* Bim    = (const float*)d_in[4];
    const float* Cre    = (const float*)d_in[5];
    const float* Cim    = (const float*)d_in[6];
    const float* D      = (const float*)d_in[7];
    const float* bh_re  = (const float*)d_in[8];
    const float* bh_im  = (const float*)d_in[9];
    const float* bias   = (const float*)d_in[10];

    float* Y = (float*)d_out;
    float* out_hN = Y + Y_ELEMS;

    static int smem_set = 0;
    if (!smem_set) {
        cudaFuncSetAttribute(gemm1_kernel, cudaFuncAttributeMaxDynamicSharedMemorySize, SMEM_BYTES);
        cudaFuncSetAttribute(gemm2_kernel, cudaFuncAttributeMaxDynamicSharedMemorySize, SMEM_BYTES);
        smem_set = 1;
    }

    cudaStream_t s0 = 0;                 // harness capture stream (legacy)
    cudaStream_t s1 = g_ar.s1;
    const long long G4Q = (long long)MTOT * INF / 4 / NQ;   // convx threads per quarter

    // s0: prep + wprep, then fork s1
    prep_kernel<<<1, HF, 0, s0>>>(nu_log, th_log, bh_re, bh_im);
    int wtot = 1024 * 256 + 256 * K2;
    wprep_kernel<<<(wtot + 255) / 256, 256, 0, s0>>>(Bre, Bim, Cre, Cim, D);
    cudaEventRecord(g_ar.evFork, s0);
    cudaStreamWaitEvent(s1, g_ar.evFork, 0);

    // s1: convx quarters 1..3 (only need X)
    for (int q = 1; q < NQ; q++) {
        convx_kernel<<<(int)(G4Q / 256), 256, 0, s1>>>(X, q * G4Q);
        cudaEventRecord(g_ar.evC[q], s1);
    }

    // s0: convx_q0 then gemm1 quarters (waiting on convx of that quarter)
    convx_kernel<<<(int)(G4Q / 256), 256, 0, s0>>>(X, 0);
    for (int q = 0; q < NQ; q++) {
        if (q > 0) cudaStreamWaitEvent(s0, g_ar.evC[q], 0);
        dim3 g1(8, MQ / 128);
        gemm1_kernel<<<g1, 128, SMEM_BYTES, s0>>>(q * (MQ / 128));
        cudaEventRecord(g_ar.evG1[q], s0);
    }

    // s1: scan quarters (wait for their gemm1)
    for (int q = 0; q < NQ; q++) {
        cudaStreamWaitEvent(s1, g_ar.evG1[q], 0);
        scan_kernel<<<(BQ * 16 * HF) / 256, 256, 0, s1>>>(out_hN, q * BQ);
        cudaEventRecord(g_ar.evS[q], s1);
    }

    // s0: gemm2 quarters (wait for their scan) — joins s1 back into capture
    for (int q = 0; q < NQ; q++) {
        cudaStreamWaitEvent(s0, g_ar.evS[q], 0);
        dim3 g2(2, MQ / 128);
        gemm2_kernel<<<g2, 128, SMEM_BYTES, s0>>>(bias, Y, q * (MQ / 128));
    }
}

// round 14
// speedup vs baseline: 1.5143x; 1.5143x over previous
#include <cuda_runtime.h>
#include <cuda_fp16.h>
#include <math.h>
#include <stdint.h>

// Problem constants
#define BATCH 16
#define TT    4096
#define INF   256
#define OUTF  256
#define HF    512
#define MTOT  (BATCH * TT)              // 65536
#define K2    1280                      // GEMM2 K = 1024 interleaved ys + 256 X
#define Y_ELEMS ((long long)MTOT * OUTF)

// ---------------------------------------------------------------------------
// Scratch (__device__ globals; no allocation APIs)
// ---------------------------------------------------------------------------
__device__ __align__(16) __half2 g_U2[(size_t)MTOT * HF];     // interleaved (re,im) u
__device__ __align__(16) __half  g_A2[(size_t)MTOT * K2];     // fp16 activations
__device__ __align__(16) __half  g_B[1024 * 256];             // interleaved Bcat rows
__device__ __align__(16) __half  g_W[256 * K2];               // interleaved W cols
__device__ float2 g_lam[HF];
__device__ float2 g_cvec[HF];
__device__ float  g_gamma[HF];

// ---------------------------------------------------------------------------
// PTX helpers (generic PTX only; no sm_103a-only features)
// ---------------------------------------------------------------------------
__device__ __forceinline__ uint32_t smem_u32(const void* p) {
    uint32_t a;
    asm("{ .reg .u64 t; cvta.to.shared.u64 t, %1; cvt.u32.u64 %0, t; }" : "=r"(a) : "l"(p));
    return a;
}
__device__ __forceinline__ void ldsm_x4(uint32_t* r, uint32_t addr) {
    asm volatile("ldmatrix.sync.aligned.m8n8.x4.shared.b16 {%0,%1,%2,%3}, [%4];"
                 : "=r"(r[0]), "=r"(r[1]), "=r"(r[2]), "=r"(r[3]) : "r"(addr));
}
__device__ __forceinline__ void mma16816(float* c, const uint32_t* a, uint32_t b0, uint32_t b1) {
    asm volatile(
        "mma.sync.aligned.m16n8k16.row.col.f32.f16.f16.f32 "
        "{%0,%1,%2,%3}, {%4,%5,%6,%7}, {%8,%9}, {%0,%1,%2,%3};"
        : "+f"(c[0]), "+f"(c[1]), "+f"(c[2]), "+f"(c[3])
        : "r"(a[0]), "r"(a[1]), "r"(a[2]), "r"(a[3]), "r"(b0), "r"(b1));
}
__device__ __forceinline__ void cp_async16(uint32_t sdst, const void* gsrc) {
    asm volatile("cp.async.cg.shared.global [%0], [%1], 16;"
                 :: "r"(sdst), "l"(__cvta_generic_to_global(gsrc)) : "memory");
}
#define CP_COMMIT()  asm volatile("cp.async.commit_group;" ::: "memory")
#define CP_WAIT(n)   asm volatile("cp.async.wait_group %0;" :: "n"(n) : "memory")

// ---------------------------------------------------------------------------
// SMEM: 2 stages x 2 tiles of 128 rows x 32 fp16, row stride 80 B
// ---------------------------------------------------------------------------
#define TSTR   80
#define TILE_B (128 * TSTR)             // 10240
#define S_A    0
#define S_B    (TILE_B)
#define STAGE_B (2 * TILE_B)            // 20480
#define SMEM_BYTES (2 * STAGE_B)        // 40960

// 128 threads: 512 16B units, 4 iters.
__device__ __forceinline__ void ld_tile_async(uint32_t sbase, const __half* __restrict__ g,
                                              int ld, int tid) {
#pragma unroll
    for (int it = 0; it < 4; it++) {
        int u = tid + it * 128;
        int r = u >> 2, j = u & 3;
        cp_async16(sbase + r * TSTR + j * 16, g + (size_t)r * ld + j * 8);
    }
}

__device__ __forceinline__ void ld_stage(uint32_t sb,
                                         const __half* A, int lda,
                                         const __half* B, int ldb,
                                         int kc, int tid) {
    ld_tile_async(sb + S_A, A + kc * 32, lda, tid);
    ld_tile_async(sb + S_B, B + kc * 32, ldb, tid);
}

// Compute one BK=32 chunk with 64x64 warp tiles (4 warps, 2m x 2n grid).
__device__ __forceinline__ void compute_chunk(float acc[4][8][4], uint32_t sb,
                                              int lane, int wm, int wn) {
    const uint32_t a_coff = (uint32_t)((lane >> 4) << 4);
    const int a_rl = lane & 15;
    const int b_rowl = (lane & 7) + ((lane >> 4) << 3);
    const uint32_t b_coff = (uint32_t)(((lane >> 3) & 1) << 4);

#pragma unroll
    for (int k16 = 0; k16 < 2; k16++) {
        const uint32_t koff = (uint32_t)(k16 * 32);
        uint32_t ah[4][4], bx[4][4];

#pragma unroll
        for (int mf = 0; mf < 4; mf++)
            ldsm_x4(ah[mf], sb + S_A + (uint32_t)(wm * 64 + mf * 16 + a_rl) * TSTR + koff + a_coff);
#pragma unroll
        for (int ng = 0; ng < 4; ng++)
            ldsm_x4(bx[ng], sb + S_B + (uint32_t)(wn * 64 + ng * 16 + b_rowl) * TSTR + koff + b_coff);

#pragma unroll
        for (int mf = 0; mf < 4; mf++)
#pragma unroll
            for (int ng = 0; ng < 4; ng++) {
                mma16816(acc[mf][2 * ng],     ah[mf], bx[ng][0], bx[ng][1]);
                mma16816(acc[mf][2 * ng + 1], ah[mf], bx[ng][2], bx[ng][3]);
            }
    }
}

// Double-buffered GEMM core (128 threads).
__device__ __forceinline__ void gemm_core(
    float acc[4][8][4],
    const __half* __restrict__ A, int lda,
    const __half* __restrict__ B, int ldb,
    int kChunks, uint32_t sb, int tid) {

    const int lane = tid & 31;
    const int warp = tid >> 5;
    const int wm = warp & 1, wn = warp >> 1;

    ld_stage(sb, A, lda, B, ldb, 0, tid);
    CP_COMMIT();

    for (int kc = 0; kc < kChunks; kc++) {
        if (kc + 1 < kChunks) {
            ld_stage(sb + ((kc + 1) & 1) * STAGE_B, A, lda, B, ldb, kc + 1, tid);
            CP_COMMIT();
            CP_WAIT(1);
        } else {
            CP_WAIT(0);
        }
        __syncthreads();
        compute_chunk(acc, sb + (kc & 1) * STAGE_B, lane, wm, wn);
        __syncthreads();
    }
}

// ---------------------------------------------------------------------------
// wprep (+ fused lambda/gamma prep for n < 512).
// B rows interleaved: row 2h = Bre[h], row 2h+1 = Bim[h] (1024x256).
// W cols interleaved: col 2h = Cre[o][h], col 2h+1 = -Cim[o][h], cols 1024+ = D.
// ---------------------------------------------------------------------------
__global__ void wprep_kernel(const float* __restrict__ Bre, const float* __restrict__ Bim,
                             const float* __restrict__ Cre, const float* __restrict__ Cim,
                             const float* __restrict__ D,
                             const float* __restrict__ nu_log,
                             const float* __restrict__ theta_log,
                             const float* __restrict__ bh_re,
                             const float* __restrict__ bh_im) {
    int n = blockIdx.x * blockDim.x + threadIdx.x;
    if (n < HF) {
        float en = expf(nu_log[n]);
        float et = expf(theta_log[n]);
        float mag = expf(-en);
        float s, c;
        sincosf(et, &s, &c);
        g_lam[n] = make_float2(mag * c, mag * s);
        float gam = sqrtf(fmaxf(0.0f, 1.0f - mag * mag));
        g_gamma[n] = gam;
        g_cvec[n] = make_float2((gam + 1.0f) * bh_re[n], (gam + 1.0f) * bh_im[n]);
    }
    if (n < 1024 * 256) {
        int r = n >> 8, i = n & 255;
        int h = r >> 1;
        float v = (r & 1) ? Bim[h * 256 + i] : Bre[h * 256 + i];
        g_B[n] = __float2half(v);
    } else {
        int n2 = n - 1024 * 256;
        if (n2 < 256 * K2) {
            int o = n2 / K2, k = n2 % K2;
            float v;
            if (k < 1024) {
                int h = k >> 1;
                v = (k & 1) ? -Cim[o * 512 + h] : Cre[o * 512 + h];
            } else {
                v = D[o * 256 + (k - 1024)];
            }
            g_W[n2] = __float2half(v);
        }
    }
}

// X -> fp16 into A2 cols [1024..1279]. 8 floats per thread, one 16B store.
__global__ void convx_kernel(const float* __restrict__ X) {
    long long g8 = (long long)blockIdx.x * blockDim.x + threadIdx.x;
    if (g8 >= (long long)MTOT * INF / 8) return;
    int m = (int)(g8 >> 5), i = (int)(g8 & 31) * 8;
    const float4* xp = reinterpret_cast<const float4*>(X + (size_t)m * INF + i);
    float4 v0 = xp[0];
    float4 v1 = xp[1];
    __half2 p[4];
    p[0] = __floats2half2_rn(v0.x, v0.y);
    p[1] = __floats2half2_rn(v0.z, v0.w);
    p[2] = __floats2half2_rn(v1.x, v1.y);
    p[3] = __floats2half2_rn(v1.z, v1.w);
    *reinterpret_cast<uint4*>(g_A2 + (size_t)m * K2 + 1024 + i) = *reinterpret_cast<uint4*>(p);
}

// ---------------------------------------------------------------------------
// GEMM1: u(re,im) interleaved = gamma * (X_f16 . BcatT). Output: g_U2.
// ---------------------------------------------------------------------------
__global__ __launch_bounds__(128, 2) void gemm1_kernel() {
    extern __shared__ char smem[];
    uint32_t sb = smem_u32(smem);
    const int tid = threadIdx.x;
    const int lane = tid & 31;
    const int warp = tid >> 5;
    const int wm = warp & 1, wn = warp >> 1;
    const int mBase = blockIdx.y * 128;
    const int colBase = blockIdx.x * 128;

    float acc[4][8][4];
#pragma unroll
    for (int a = 0; a < 4; a++)
#pragma unroll
        for (int b = 0; b < 8; b++)
#pragma unroll
            for (int c = 0; c < 4; c++) acc[a][b][c] = 0.f;

    gemm_core(acc,
              g_A2 + (size_t)mBase * K2 + 1024, K2,
              g_B + (size_t)colBase * 256, 256,
              8, sb, tid);

#pragma unroll
    for (int mf = 0; mf < 4; mf++) {
        int m0 = mBase + wm * 64 + mf * 16 + (lane >> 2);
#pragma unroll
        for (int nf = 0; nf < 8; nf++) {
            int col = colBase + wn * 64 + nf * 8 + (lane & 3) * 2;   // even
            int h = col >> 1;
            float g = g_gamma[h];
            float* c = acc[mf][nf];
            g_U2[(size_t)m0 * HF + h]       = __floats2half2_rn(c[0] * g, c[1] * g);
            g_U2[(size_t)(m0 + 8) * HF + h] = __floats2half2_rn(c[2] * g, c[3] * g);
        }
    }
}

// ---------------------------------------------------------------------------
// Scan: chunked-parallel, 16 chunks of 256 (+32 warmup; lambda^32 ~ 1e-14).
// 4 h-channels per thread: one 16B load + one 16B store per t-step,
// 4 independent complex recurrences (ILP). Math identical to scalar version.
// ---------------------------------------------------------------------------
#define SCH   256
#define SWARM 32
__global__ __launch_bounds__(128) void scan_kernel(float* __restrict__ out_hN) {
    int g = blockIdx.x * blockDim.x + threadIdx.x;   // 0..32767
    int hq = g & 127;            // h quad: channels h0..h0+3
    int ch = (g >> 7) & 15;
    int b = g >> 11;
    int h0 = hq * 4;

    float lr[4], li[4], cr[4], ci[4], hr[4], hi[4];
#pragma unroll
    for (int k = 0; k < 4; k++) {
        float2 lam = g_lam[h0 + k];
        float2 cv = g_cvec[h0 + k];
        lr[k] = lam.x; li[k] = lam.y;
        cr[k] = cv.x;  ci[k] = cv.y;
        hr[k] = 0.f;   hi[k] = 0.f;
    }

    const int t0 = ch * SCH;
    const int tw = (ch == 0) ? 0 : t0 - SWARM;
    const __half2* up = g_U2 + ((size_t)b * TT + tw) * HF + h0;

    for (int t = tw; t < t0; t++) {
        uint4 raw = *reinterpret_cast<const uint4*>(up);
        const __half2* vh = reinterpret_cast<const __half2*>(&raw);
#pragma unroll
        for (int k = 0; k < 4; k++) {
            float2 v = __half22float2(vh[k]);
            float vr = v.x + cr[k];
            float vi = v.y + ci[k];
            float nr = fmaf(lr[k], hr[k], fmaf(-li[k], hi[k], vr));
            float ni = fmaf(lr[k], hi[k], fmaf(li[k], hr[k], vi));
            hr[k] = nr; hi[k] = ni;
        }
        up += HF;
    }

    __half* ap = g_A2 + ((size_t)b * TT + t0) * K2 + 2 * h0;
    for (int t = 0; t < SCH; t++) {
        uint4 raw = *reinterpret_cast<const uint4*>(up);
        const __half2* vh = reinterpret_cast<const __half2*>(&raw);
        __half2 out[4];
#pragma unroll
        for (int k = 0; k < 4; k++) {
            float2 v = __half22float2(vh[k]);
            float vr = v.x + cr[k];
            float vi = v.y + ci[k];
            float nr = fmaf(lr[k], hr[k], fmaf(-li[k], hi[k], vr));
            float ni = fmaf(lr[k], hi[k], fmaf(li[k], hr[k], vi));
            hr[k] = nr; hi[k] = ni;
            out[k] = __floats2half2_rn(nr, ni);
        }
        *reinterpret_cast<uint4*>(ap) = *reinterpret_cast<uint4*>(out);
        up += HF;
        ap += K2;
    }

    if (ch == 15) {
#pragma unroll
        for (int k = 0; k < 4; k++) {
            int g2 = b * 512 + h0 + k;
            out_hN[g2] = hr[k];
            out_hN[BATCH * HF + g2] = hi[k];
        }
    }
}

// ---------------------------------------------------------------------------
// GEMM2: Y[m, 256] = A2 . WcatT + bias   (K = 1280)
// ---------------------------------------------------------------------------
__global__ __launch_bounds__(128, 2) void gemm2_kernel(const float* __restrict__ bias,
                                                       float* __restrict__ Y) {
    extern __shared__ char smem[];
    uint32_t sb = smem_u32(smem);
    const int tid = threadIdx.x;
    const int lane = tid & 31;
    const int warp = tid >> 5;
    const int wm = warp & 1, wn = warp >> 1;
    const int mBase = blockIdx.y * 128;
    const int colBase = blockIdx.x * 128;

    float acc[4][8][4];
#pragma unroll
    for (int a = 0; a < 4; a++)
#pragma unroll
        for (int b = 0; b < 8; b++)
#pragma unroll
            for (int c = 0; c < 4; c++) acc[a][b][c] = 0.f;

    gemm_core(acc,
              g_A2 + (size_t)mBase * K2, K2,
              g_W + (size_t)colBase * K2, K2,
              40, sb, tid);

#pragma unroll
    for (int mf = 0; mf < 4; mf++) {
        int m0 = mBase + wm * 64 + mf * 16 + (lane >> 2);
#pragma unroll
        for (int nf = 0; nf < 8; nf++) {
            int col = colBase + wn * 64 + nf * 8 + (lane & 3) * 2;
            float b0 = bias[col], b1 = bias[col + 1];
            float* c = acc[mf][nf];
            *reinterpret_cast<float2*>(&Y[(size_t)m0 * OUTF + col]) =
                make_float2(c[0] + b0, c[1] + b1);
            *reinterpret_cast<float2*>(&Y[(size_t)(m0 + 8) * OUTF + col]) =
                make_float2(c[2] + b0, c[3] + b1);
        }
    }
}

// ---------------------------------------------------------------------------
// Launch (single stream — R11 structure)
// ---------------------------------------------------------------------------
extern "C" void kernel_launch(void* const* d_in, const int* in_sizes, int n_in,
                              void* d_out, int out_size) {
    const float* X      = (const float*)d_in[0];
    const float* nu_log = (const float*)d_in[1];
    const float* th_log = (const float*)d_in[2];
    const float* Bre    = (const float*)d_in[3];
    const float* Bim    = (const float*)d_in[4];
    const float* Cre    = (const float*)d_in[5];
    const float* Cim    = (const float*)d_in[6];
    const float* D      = (const float*)d_in[7];
    const float* bh_re  = (const float*)d_in[8];
    const float* bh_im  = (const float*)d_in[9];
    const float* bias   = (const float*)d_in[10];

    float* Y = (float*)d_out;
    float* out_hN = Y + Y_ELEMS;

    static int smem_set = 0;
    if (!smem_set) {
        cudaFuncSetAttribute(gemm1_kernel, cudaFuncAttributeMaxDynamicSharedMemorySize, SMEM_BYTES);
        cudaFuncSetAttribute(gemm2_kernel, cudaFuncAttributeMaxDynamicSharedMemorySize, SMEM_BYTES);
        smem_set = 1;
    }

    int wtot = 1024 * 256 + 256 * K2;
    wprep_kernel<<<(wtot + 255) / 256, 256>>>(Bre, Bim, Cre, Cim, D,
                                              nu_log, th_log, bh_re, bh_im);

    convx_kernel<<<(int)((MTOT * (long long)INF / 8 + 255) / 256), 256>>>(X);

    dim3 g1(8, MTOT / 128);
    gemm1_kernel<<<g1, 128, SMEM_BYTES>>>();

    scan_kernel<<<(BATCH * 16 * 128) / 128, 128>>>(out_hN);

    dim3 g2(2, MTOT / 128);
    gemm2_kernel<<<g2, 128, SMEM_BYTES>>>(bias, Y);
}

// round 15
// speedup vs baseline: 1.8011x; 1.1894x over previous
#include <cuda_runtime.h>
#include <cuda_fp16.h>
#include <math.h>
#include <stdint.h>

// Problem constants
#define BATCH 16
#define TT    4096
#define INF   256
#define OUTF  256
#define HF    512
#define MTOT  (BATCH * TT)              // 65536
#define K2    1280                      // GEMM2 K = 1024 interleaved ys + 256 X
#define Y_ELEMS ((long long)MTOT * OUTF)

// ---------------------------------------------------------------------------
// Scratch (__device__ globals; no allocation APIs)
// ---------------------------------------------------------------------------
__device__ __align__(16) __half2 g_U2[(size_t)MTOT * HF];     // interleaved (re,im) u
__device__ __align__(16) __half  g_A2[(size_t)MTOT * K2];     // fp16 activations
__device__ __align__(16) __half  g_B[1024 * 256];             // interleaved Bcat rows
__device__ __align__(16) __half  g_W[256 * K2];               // interleaved W cols
__device__ float2 g_lam[HF];
__device__ float2 g_cvec[HF];
__device__ float  g_gamma[HF];

// ---------------------------------------------------------------------------
// PTX helpers (generic PTX only; no sm_103a-only features)
// ---------------------------------------------------------------------------
__device__ __forceinline__ uint32_t smem_u32(const void* p) {
    uint32_t a;
    asm("{ .reg .u64 t; cvta.to.shared.u64 t, %1; cvt.u32.u64 %0, t; }" : "=r"(a) : "l"(p));
    return a;
}
__device__ __forceinline__ void ldsm_x4(uint32_t* r, uint32_t addr) {
    asm volatile("ldmatrix.sync.aligned.m8n8.x4.shared.b16 {%0,%1,%2,%3}, [%4];"
                 : "=r"(r[0]), "=r"(r[1]), "=r"(r[2]), "=r"(r[3]) : "r"(addr));
}
__device__ __forceinline__ void mma16816(float* c, const uint32_t* a, uint32_t b0, uint32_t b1) {
    asm volatile(
        "mma.sync.aligned.m16n8k16.row.col.f32.f16.f16.f32 "
        "{%0,%1,%2,%3}, {%4,%5,%6,%7}, {%8,%9}, {%0,%1,%2,%3};"
        : "+f"(c[0]), "+f"(c[1]), "+f"(c[2]), "+f"(c[3])
        : "r"(a[0]), "r"(a[1]), "r"(a[2]), "r"(a[3]), "r"(b0), "r"(b1));
}
__device__ __forceinline__ void cp_async16(uint32_t sdst, const void* gsrc) {
    asm volatile("cp.async.cg.shared.global [%0], [%1], 16;"
                 :: "r"(sdst), "l"(__cvta_generic_to_global(gsrc)) : "memory");
}
#define CP_COMMIT()  asm volatile("cp.async.commit_group;" ::: "memory")
#define CP_WAIT(n)   asm volatile("cp.async.wait_group %0;" :: "n"(n) : "memory")

// ---------------------------------------------------------------------------
// SMEM: 2 stages x 2 tiles of 128 rows x 32 fp16, row stride 80 B
// ---------------------------------------------------------------------------
#define TSTR   80
#define TILE_B (128 * TSTR)             // 10240
#define S_A    0
#define S_B    (TILE_B)
#define STAGE_B (2 * TILE_B)            // 20480
#define SMEM_BYTES (2 * STAGE_B)        // 40960

// 128 threads: 512 16B units, 4 iters.
__device__ __forceinline__ void ld_tile_async(uint32_t sbase, const __half* __restrict__ g,
                                              int ld, int tid) {
#pragma unroll
    for (int it = 0; it < 4; it++) {
        int u = tid + it * 128;
        int r = u >> 2, j = u & 3;
        cp_async16(sbase + r * TSTR + j * 16, g + (size_t)r * ld + j * 8);
    }
}

__device__ __forceinline__ void ld_stage(uint32_t sb,
                                         const __half* A, int lda,
                                         const __half* B, int ldb,
                                         int kc, int tid) {
    ld_tile_async(sb + S_A, A + kc * 32, lda, tid);
    ld_tile_async(sb + S_B, B + kc * 32, ldb, tid);
}

// Compute one BK=32 chunk with 64x64 warp tiles (4 warps, 2m x 2n grid).
__device__ __forceinline__ void compute_chunk(float acc[4][8][4], uint32_t sb,
                                              int lane, int wm, int wn) {
    const uint32_t a_coff = (uint32_t)((lane >> 4) << 4);
    const int a_rl = lane & 15;
    const int b_rowl = (lane & 7) + ((lane >> 4) << 3);
    const uint32_t b_coff = (uint32_t)(((lane >> 3) & 1) << 4);

#pragma unroll
    for (int k16 = 0; k16 < 2; k16++) {
        const uint32_t koff = (uint32_t)(k16 * 32);
        uint32_t ah[4][4], bx[4][4];

#pragma unroll
        for (int mf = 0; mf < 4; mf++)
            ldsm_x4(ah[mf], sb + S_A + (uint32_t)(wm * 64 + mf * 16 + a_rl) * TSTR + koff + a_coff);
#pragma unroll
        for (int ng = 0; ng < 4; ng++)
            ldsm_x4(bx[ng], sb + S_B + (uint32_t)(wn * 64 + ng * 16 + b_rowl) * TSTR + koff + b_coff);

#pragma unroll
        for (int mf = 0; mf < 4; mf++)
#pragma unroll
            for (int ng = 0; ng < 4; ng++) {
                mma16816(acc[mf][2 * ng],     ah[mf], bx[ng][0], bx[ng][1]);
                mma16816(acc[mf][2 * ng + 1], ah[mf], bx[ng][2], bx[ng][3]);
            }
    }
}

// Double-buffered GEMM core (128 threads).
__device__ __forceinline__ void gemm_core(
    float acc[4][8][4],
    const __half* __restrict__ A, int lda,
    const __half* __restrict__ B, int ldb,
    int kChunks, uint32_t sb, int tid) {

    const int lane = tid & 31;
    const int warp = tid >> 5;
    const int wm = warp & 1, wn = warp >> 1;

    ld_stage(sb, A, lda, B, ldb, 0, tid);
    CP_COMMIT();

    for (int kc = 0; kc < kChunks; kc++) {
        if (kc + 1 < kChunks) {
            ld_stage(sb + ((kc + 1) & 1) * STAGE_B, A, lda, B, ldb, kc + 1, tid);
            CP_COMMIT();
            CP_WAIT(1);
        } else {
            CP_WAIT(0);
        }
        __syncthreads();
        compute_chunk(acc, sb + (kc & 1) * STAGE_B, lane, wm, wn);
        __syncthreads();
    }
}

// ---------------------------------------------------------------------------
// wprep (+ fused lambda/gamma prep for n < 512).
// ---------------------------------------------------------------------------
__global__ void wprep_kernel(const float* __restrict__ Bre, const float* __restrict__ Bim,
                             const float* __restrict__ Cre, const float* __restrict__ Cim,
                             const float* __restrict__ D,
                             const float* __restrict__ nu_log,
                             const float* __restrict__ theta_log,
                             const float* __restrict__ bh_re,
                             const float* __restrict__ bh_im) {
    int n = blockIdx.x * blockDim.x + threadIdx.x;
    if (n < HF) {
        float en = expf(nu_log[n]);
        float et = expf(theta_log[n]);
        float mag = expf(-en);
        float s, c;
        sincosf(et, &s, &c);
        g_lam[n] = make_float2(mag * c, mag * s);
        float gam = sqrtf(fmaxf(0.0f, 1.0f - mag * mag));
        g_gamma[n] = gam;
        g_cvec[n] = make_float2((gam + 1.0f) * bh_re[n], (gam + 1.0f) * bh_im[n]);
    }
    if (n < 1024 * 256) {
        int r = n >> 8, i = n & 255;
        int h = r >> 1;
        float v = (r & 1) ? Bim[h * 256 + i] : Bre[h * 256 + i];
        g_B[n] = __float2half(v);
    } else {
        int n2 = n - 1024 * 256;
        if (n2 < 256 * K2) {
            int o = n2 / K2, k = n2 % K2;
            float v;
            if (k < 1024) {
                int h = k >> 1;
                v = (k & 1) ? -Cim[o * 512 + h] : Cre[o * 512 + h];
            } else {
                v = D[o * 256 + (k - 1024)];
            }
            g_W[n2] = __float2half(v);
        }
    }
}

// X -> fp16 into A2 cols [1024..1279]. 8 floats per thread, one 16B store.
__global__ void convx_kernel(const float* __restrict__ X) {
    long long g8 = (long long)blockIdx.x * blockDim.x + threadIdx.x;
    if (g8 >= (long long)MTOT * INF / 8) return;
    int m = (int)(g8 >> 5), i = (int)(g8 & 31) * 8;
    const float4* xp = reinterpret_cast<const float4*>(X + (size_t)m * INF + i);
    float4 v0 = xp[0];
    float4 v1 = xp[1];
    __half2 p[4];
    p[0] = __floats2half2_rn(v0.x, v0.y);
    p[1] = __floats2half2_rn(v0.z, v0.w);
    p[2] = __floats2half2_rn(v1.x, v1.y);
    p[3] = __floats2half2_rn(v1.z, v1.w);
    *reinterpret_cast<uint4*>(g_A2 + (size_t)m * K2 + 1024 + i) = *reinterpret_cast<uint4*>(p);
}

// ---------------------------------------------------------------------------
// GEMM1: u(re,im) interleaved = gamma * (X_f16 . BcatT). Output: g_U2.
// ---------------------------------------------------------------------------
__global__ __launch_bounds__(128, 2) void gemm1_kernel() {
    extern __shared__ char smem[];
    uint32_t sb = smem_u32(smem);
    const int tid = threadIdx.x;
    const int lane = tid & 31;
    const int warp = tid >> 5;
    const int wm = warp & 1, wn = warp >> 1;
    const int mBase = blockIdx.y * 128;
    const int colBase = blockIdx.x * 128;

    float acc[4][8][4];
#pragma unroll
    for (int a = 0; a < 4; a++)
#pragma unroll
        for (int b = 0; b < 8; b++)
#pragma unroll
            for (int c = 0; c < 4; c++) acc[a][b][c] = 0.f;

    gemm_core(acc,
              g_A2 + (size_t)mBase * K2 + 1024, K2,
              g_B + (size_t)colBase * 256, 256,
              8, sb, tid);

#pragma unroll
    for (int mf = 0; mf < 4; mf++) {
        int m0 = mBase + wm * 64 + mf * 16 + (lane >> 2);
#pragma unroll
        for (int nf = 0; nf < 8; nf++) {
            int col = colBase + wn * 64 + nf * 8 + (lane & 3) * 2;   // even
            int h = col >> 1;
            float g = g_gamma[h];
            float* c = acc[mf][nf];
            g_U2[(size_t)m0 * HF + h]       = __floats2half2_rn(c[0] * g, c[1] * g);
            g_U2[(size_t)(m0 + 8) * HF + h] = __floats2half2_rn(c[2] * g, c[3] * g);
        }
    }
}

// ---------------------------------------------------------------------------
// Scan: chunked-parallel, 32 chunks of 128 (+32 warmup; lambda^32 ~ 1e-14).
// 2 h-channels per thread: 8B load + 8B store per step, 2-way ILP,
// 131072 threads for latency hiding.
// ---------------------------------------------------------------------------
#define SCH   128
#define SWARM 32
__global__ __launch_bounds__(256) void scan_kernel(float* __restrict__ out_hN) {
    int g = blockIdx.x * blockDim.x + threadIdx.x;   // 0..131071
    int hp = g & 255;            // h pair index: channels 2*hp, 2*hp+1
    int ch = (g >> 8) & 31;      // chunk 0..31
    int b = g >> 13;             // batch
    int h0 = hp * 2;

    float lr[2], li[2], cr[2], ci[2], hr[2], hi[2];
#pragma unroll
    for (int k = 0; k < 2; k++) {
        float2 lam = g_lam[h0 + k];
        float2 cv = g_cvec[h0 + k];
        lr[k] = lam.x; li[k] = lam.y;
        cr[k] = cv.x;  ci[k] = cv.y;
        hr[k] = 0.f;   hi[k] = 0.f;
    }

    const int t0 = ch * SCH;
    const int tw = (ch == 0) ? 0 : t0 - SWARM;
    const __half2* up = g_U2 + ((size_t)b * TT + tw) * HF + h0;

    for (int t = tw; t < t0; t++) {
        uint2 raw = *reinterpret_cast<const uint2*>(up);
        const __half2* vh = reinterpret_cast<const __half2*>(&raw);
#pragma unroll
        for (int k = 0; k < 2; k++) {
            float2 v = __half22float2(vh[k]);
            float vr = v.x + cr[k];
            float vi = v.y + ci[k];
            float nr = fmaf(lr[k], hr[k], fmaf(-li[k], hi[k], vr));
            float ni = fmaf(lr[k], hi[k], fmaf(li[k], hr[k], vi));
            hr[k] = nr; hi[k] = ni;
        }
        up += HF;
    }

    __half* ap = g_A2 + ((size_t)b * TT + t0) * K2 + 2 * h0;
    for (int t = 0; t < SCH; t++) {
        uint2 raw = *reinterpret_cast<const uint2*>(up);
        const __half2* vh = reinterpret_cast<const __half2*>(&raw);
        __half2 out[2];
#pragma unroll
        for (int k = 0; k < 2; k++) {
            float2 v = __half22float2(vh[k]);
            float vr = v.x + cr[k];
            float vi = v.y + ci[k];
            float nr = fmaf(lr[k], hr[k], fmaf(-li[k], hi[k], vr));
            float ni = fmaf(lr[k], hi[k], fmaf(li[k], hr[k], vi));
            hr[k] = nr; hi[k] = ni;
            out[k] = __floats2half2_rn(nr, ni);
        }
        *reinterpret_cast<uint2*>(ap) = *reinterpret_cast<uint2*>(out);
        up += HF;
        ap += K2;
    }

    if (ch == 31) {
#pragma unroll
        for (int k = 0; k < 2; k++) {
            int g2 = b * 512 + h0 + k;
            out_hN[g2] = hr[k];
            out_hN[BATCH * HF + g2] = hi[k];
        }
    }
}

// ---------------------------------------------------------------------------
// GEMM2: Y[m, 256] = A2 . WcatT + bias   (K = 1280)
// ---------------------------------------------------------------------------
__global__ __launch_bounds__(128, 2) void gemm2_kernel(const float* __restrict__ bias,
                                                       float* __restrict__ Y) {
    extern __shared__ char smem[];
    uint32_t sb = smem_u32(smem);
    const int tid = threadIdx.x;
    const int lane = tid & 31;
    const int warp = tid >> 5;
    const int wm = warp & 1, wn = warp >> 1;
    const int mBase = blockIdx.y * 128;
    const int colBase = blockIdx.x * 128;

    float acc[4][8][4];
#pragma unroll
    for (int a = 0; a < 4; a++)
#pragma unroll
        for (int b = 0; b < 8; b++)
#pragma unroll
            for (int c = 0; c < 4; c++) acc[a][b][c] = 0.f;

    gemm_core(acc,
              g_A2 + (size_t)mBase * K2, K2,
              g_W + (size_t)colBase * K2, K2,
              40, sb, tid);

#pragma unroll
    for (int mf = 0; mf < 4; mf++) {
        int m0 = mBase + wm * 64 + mf * 16 + (lane >> 2);
#pragma unroll
        for (int nf = 0; nf < 8; nf++) {
            int col = colBase + wn * 64 + nf * 8 + (lane & 3) * 2;
            float b0 = bias[col], b1 = bias[col + 1];
            float* c = acc[mf][nf];
            *reinterpret_cast<float2*>(&Y[(size_t)m0 * OUTF + col]) =
                make_float2(c[0] + b0, c[1] + b1);
            *reinterpret_cast<float2*>(&Y[(size_t)(m0 + 8) * OUTF + col]) =
                make_float2(c[2] + b0, c[3] + b1);
        }
    }
}

// ---------------------------------------------------------------------------
// Launch (single stream)
// ---------------------------------------------------------------------------
extern "C" void kernel_launch(void* const* d_in, const int* in_sizes, int n_in,
                              void* d_out, int out_size) {
    const float* X      = (const float*)d_in[0];
    const float* nu_log = (const float*)d_in[1];
    const float* th_log = (const float*)d_in[2];
    const float* Bre    = (const float*)d_in[3];
    const float* Bim    = (const float*)d_in[4];
    const float* Cre    = (const float*)d_in[5];
    const float* Cim    = (const float*)d_in[6];
    const float* D      = (const float*)d_in[7];
    const float* bh_re  = (const float*)d_in[8];
    const float* bh_im  = (const float*)d_in[9];
    const float* bias   = (const float*)d_in[10];

    float* Y = (float*)d_out;
    float* out_hN = Y + Y_ELEMS;

    static int smem_set = 0;
    if (!smem_set) {
        cudaFuncSetAttribute(gemm1_kernel, cudaFuncAttributeMaxDynamicSharedMemorySize, SMEM_BYTES);
        cudaFuncSetAttribute(gemm2_kernel, cudaFuncAttributeMaxDynamicSharedMemorySize, SMEM_BYTES);
        smem_set = 1;
    }

    int wtot = 1024 * 256 + 256 * K2;
    wprep_kernel<<<(wtot + 255) / 256, 256>>>(Bre, Bim, Cre, Cim, D,
                                              nu_log, th_log, bh_re, bh_im);

    convx_kernel<<<(int)((MTOT * (long long)INF / 8 + 255) / 256), 256>>>(X);

    dim3 g1(8, MTOT / 128);
    gemm1_kernel<<<g1, 128, SMEM_BYTES>>>();

    scan_kernel<<<(BATCH * 32 * 256) / 256, 256>>>(out_hN);

    dim3 g2(2, MTOT / 128);
    gemm2_kernel<<<g2, 128, SMEM_BYTES>>>(bias, Y);
}